// round 1
// baseline (speedup 1.0000x reference)
#include <cuda_runtime.h>
#include <math.h>

#define NIMG 32768
#define DIN  620

// 81.3 MB feature scratch (device global: allocation-free per harness rules)
__device__ float g_feat[(size_t)NIMG * DIN];

// ---------------------------------------------------------------------------
// Kernel A: per-image top-200 stable descending selection + feature build
// ---------------------------------------------------------------------------
__global__ __launch_bounds__(256) void topk_feat_kernel(
    const float* __restrict__ images, const float* __restrict__ angles) {
  __shared__ unsigned int vbits[784];
  __shared__ unsigned int hist[256];
  __shared__ unsigned long long keys[256];
  __shared__ int sT;
  __shared__ int cnt;

  const int b = blockIdx.x;
  const int tid = threadIdx.x;
  const float* img = images + (size_t)b * 784;

  hist[tid] = 0u;
  if (tid == 0) cnt = 0;
  __syncthreads();

  // Pass 1: load values, histogram by 8-bit quantized bucket
  for (int i = tid; i < 784; i += 256) {
    float v = img[i];
    vbits[i] = __float_as_uint(v);
    int q = min(255, (int)(v * 256.0f));
    atomicAdd(&hist[q], 1u);
  }
  __syncthreads();

  // Pass 2: warp 0 finds threshold bucket T: count(q >= T) >= 200 > count(q > T)
  if (tid < 32) {
    unsigned int g = 0;
#pragma unroll
    for (int j = 0; j < 8; j++) g += hist[tid * 8 + j];
    unsigned int suf = g;
#pragma unroll
    for (int d = 1; d < 32; d <<= 1) {
      unsigned int o = __shfl_down_sync(0xffffffffu, suf, d);
      if (tid + d < 32) suf += o;
    }
    unsigned int m = __ballot_sync(0xffffffffu, suf >= 200u);
    int L = 31 - __clz(m);  // highest lane whose suffix-sum >= 200
    unsigned int sufN = __shfl_down_sync(0xffffffffu, suf, 1);
    if (tid == L) {
      unsigned int s = (L == 31) ? 0u : sufN;  // count strictly above lane L's buckets
      int T = 8 * L;
      for (int q = 8 * L + 7; q >= 8 * L; q--) {
        s += hist[q];
        if (s >= 200u) { T = q; break; }
      }
      sT = T;
    }
  }
  __syncthreads();

  keys[tid] = ~0ULL;  // sentinel: sorts last
  const int T = sT;
  __syncthreads();

  // Pass 3: compact candidates (q >= T). key = (~bits << 10) | idx
  // ascending sort => descending value, ascending index on ties (stable argsort(-v))
  for (int i = tid; i < 784; i += 256) {
    unsigned int vb = vbits[i];
    float v = __uint_as_float(vb);
    int q = min(255, (int)(v * 256.0f));
    if (q >= T) {
      int pos = atomicAdd(&cnt, 1);
      if (pos < 256)
        keys[pos] = (((unsigned long long)(~vb)) << 10) | (unsigned long long)i;
    }
  }

  // Pass 4: bitonic sort of 256 keys
  for (int k = 2; k <= 256; k <<= 1) {
    for (int s = k >> 1; s > 0; s >>= 1) {
      __syncthreads();
      int j = tid ^ s;
      if (j > tid) {
        unsigned long long a = keys[tid];
        unsigned long long c = keys[j];
        bool asc = ((tid & k) == 0);
        if ((a > c) == asc) { keys[tid] = c; keys[j] = a; }
      }
    }
  }
  __syncthreads();

  // Pass 5: write features: [v(200) | (cx,cy)x200 | (cos,sin)x10]
  float* fo = g_feat + (size_t)b * DIN;
  if (tid < 200) {
    unsigned long long key = keys[tid];
    int idx = (int)(key & 1023ULL);
    unsigned int vb = ~((unsigned int)(key >> 10));
    float v = __uint_as_float(vb);
    int r = idx / 28;
    int c = idx - r * 28;
    float cx = (c < 14) ? (float)(c - 14) : (float)(c - 13);
    float cy = (r < 14) ? (float)(14 - r) : (float)(13 - r);
    if (v < 0.1f) { v = 0.f; cx = 0.f; cy = 0.f; }
    fo[tid] = v;
    fo[200 + 2 * tid] = cx;
    fo[201 + 2 * tid] = cy;
  } else if (tid < 210) {
    int d = tid - 200;
    float a = angles[(size_t)b * 10 + d];
    float sn, cs;
    sincosf(a, &sn, &cs);
    fo[600 + 2 * d] = cs;
    fo[601 + 2 * d] = sn;
  }
}

// ---------------------------------------------------------------------------
// Kernel B: fused 4-layer MLP + 2x2 Gram-Schmidt epilogue
// 64 batch rows per block, 96 threads, 8x8 register micro-tile per thread
// ---------------------------------------------------------------------------
__global__ __launch_bounds__(96) void mlp_kernel(
    const float* __restrict__ W1, const float* __restrict__ b1,
    const float* __restrict__ W2, const float* __restrict__ b2,
    const float* __restrict__ W3, const float* __restrict__ b3,
    const float* __restrict__ W4, const float* __restrict__ b4,
    float* __restrict__ outp) {
  __shared__ float fbuf[64 * 33];   // 31-wide k-slab of feat, padded rows
  __shared__ float hbuf[64 * 97];   // activations, padded rows

  const int tid = threadIdx.x;
  const int tc = tid % 12;   // 12 col-groups x 8 cols = 96
  const int tr = tid / 12;   // 8 row-groups  x 8 rows = 64
  const int row0 = blockIdx.x * 64;
  const float* fptr = g_feat + (size_t)row0 * DIN;

  float acc[8][8];
#pragma unroll
  for (int i = 0; i < 8; i++)
#pragma unroll
    for (int j = 0; j < 8; j++) acc[i][j] = 0.f;

  // ---- Layer 1: 620 -> 96, k streamed in 20 slabs of 31 ----
  for (int ks = 0; ks < 620; ks += 31) {
    __syncthreads();
    for (int idx = tid; idx < 64 * 31; idx += 96) {
      int r = idx / 31;
      int kk = idx - r * 31;
      fbuf[r * 33 + kk] = fptr[(size_t)r * DIN + ks + kk];
    }
    __syncthreads();
#pragma unroll 1
    for (int kk = 0; kk < 31; kk++) {
      int k = ks + kk;
      float4 wa = *(const float4*)(W1 + (size_t)k * 96 + tc * 8);
      float4 wb = *(const float4*)(W1 + (size_t)k * 96 + tc * 8 + 4);
      float f[8];
#pragma unroll
      for (int i = 0; i < 8; i++) f[i] = fbuf[(tr * 8 + i) * 33 + kk];
      float w[8] = {wa.x, wa.y, wa.z, wa.w, wb.x, wb.y, wb.z, wb.w};
#pragma unroll
      for (int i = 0; i < 8; i++)
#pragma unroll
        for (int j = 0; j < 8; j++) acc[i][j] = fmaf(f[i], w[j], acc[i][j]);
    }
  }
  __syncthreads();
  {
    float4 ba = *(const float4*)(b1 + tc * 8);
    float4 bb = *(const float4*)(b1 + tc * 8 + 4);
    float bl[8] = {ba.x, ba.y, ba.z, ba.w, bb.x, bb.y, bb.z, bb.w};
#pragma unroll
    for (int i = 0; i < 8; i++)
#pragma unroll
      for (int j = 0; j < 8; j++)
        hbuf[(tr * 8 + i) * 97 + tc * 8 + j] = fmaxf(acc[i][j] + bl[j], 0.f);
  }
  __syncthreads();

  // ---- Layers 2 & 3: 96 -> 96 (accumulate in regs, then overwrite hbuf) ----
  for (int layer = 0; layer < 2; layer++) {
    const float* W = layer ? W3 : W2;
    const float* bp = layer ? b3 : b2;
    float a2[8][8];
#pragma unroll
    for (int i = 0; i < 8; i++)
#pragma unroll
      for (int j = 0; j < 8; j++) a2[i][j] = 0.f;
#pragma unroll 1
    for (int k = 0; k < 96; k++) {
      float4 wa = *(const float4*)(W + (size_t)k * 96 + tc * 8);
      float4 wb = *(const float4*)(W + (size_t)k * 96 + tc * 8 + 4);
      float f[8];
#pragma unroll
      for (int i = 0; i < 8; i++) f[i] = hbuf[(tr * 8 + i) * 97 + k];
      float w[8] = {wa.x, wa.y, wa.z, wa.w, wb.x, wb.y, wb.z, wb.w};
#pragma unroll
      for (int i = 0; i < 8; i++)
#pragma unroll
        for (int j = 0; j < 8; j++) a2[i][j] = fmaf(f[i], w[j], a2[i][j]);
    }
    __syncthreads();  // all reads of hbuf complete before overwrite
    {
      float4 ba = *(const float4*)(bp + tc * 8);
      float4 bb = *(const float4*)(bp + tc * 8 + 4);
      float bl[8] = {ba.x, ba.y, ba.z, ba.w, bb.x, bb.y, bb.z, bb.w};
#pragma unroll
      for (int i = 0; i < 8; i++)
#pragma unroll
        for (int j = 0; j < 8; j++)
          hbuf[(tr * 8 + i) * 97 + tc * 8 + j] = fmaxf(a2[i][j] + bl[j], 0.f);
    }
    __syncthreads();
  }

  // ---- Layer 4 (96 -> 4) + Gram-Schmidt epilogue, one thread per row ----
  if (tid < 64) {
    float o0 = 0.f, o1 = 0.f, o2 = 0.f, o3 = 0.f;
#pragma unroll 4
    for (int k = 0; k < 96; k++) {
      float hv = hbuf[tid * 97 + k];
      float4 w = *(const float4*)(W4 + (size_t)k * 4);
      o0 = fmaf(hv, w.x, o0);
      o1 = fmaf(hv, w.y, o1);
      o2 = fmaf(hv, w.z, o2);
      o3 = fmaf(hv, w.w, o3);
    }
    float4 bv = *(const float4*)(b4);
    o0 += bv.x; o1 += bv.y; o2 += bv.z; o3 += bv.w;

    // gs = out^T: c0 = (o0,o1), c1 = (o2,o3)
    float n0 = 1.0f / sqrtf(o0 * o0 + o1 * o1);
    float e0x = o0 * n0, e0y = o1 * n0;
    float dt = e0x * o2 + e0y * o3;
    float u1x = o2 - dt * e0x, u1y = o3 - dt * e0y;
    float n1 = 1.0f / sqrtf(u1x * u1x + u1y * u1y);
    float e1x = u1x * n1, e1y = u1y * n1;
    float det = e0x * e1y - e1x * e0y;

    float* po = outp + (size_t)(row0 + tid) * 4;
    po[0] = e0x * det;  // q[0][0]*det
    po[1] = e1x;        // q[0][1]
    po[2] = e0y * det;  // q[1][0]*det
    po[3] = e1y;        // q[1][1]
  }
}

// ---------------------------------------------------------------------------
extern "C" void kernel_launch(void* const* d_in, const int* in_sizes, int n_in,
                              void* d_out, int out_size) {
  (void)in_sizes; (void)n_in; (void)out_size;
  const float* images = (const float*)d_in[0];
  const float* angles = (const float*)d_in[1];
  const float* W1 = (const float*)d_in[2];
  const float* b1 = (const float*)d_in[3];
  const float* W2 = (const float*)d_in[4];
  const float* b2 = (const float*)d_in[5];
  const float* W3 = (const float*)d_in[6];
  const float* b3 = (const float*)d_in[7];
  const float* W4 = (const float*)d_in[8];
  const float* b4 = (const float*)d_in[9];
  float* outp = (float*)d_out;

  topk_feat_kernel<<<NIMG, 256>>>(images, angles);
  mlp_kernel<<<NIMG / 64, 96>>>(W1, b1, W2, b2, W3, b3, W4, b4, outp);
}

// round 2
// speedup vs baseline: 1.4979x; 1.4979x over previous
#include <cuda_runtime.h>
#include <math.h>

#define NIMG 32768
#define DIN  620

// 81.3 MB feature scratch (device global: allocation-free per harness rules)
__device__ float g_feat[(size_t)NIMG * DIN];

// ---------------------------------------------------------------------------
// Kernel A: per-image top-200 stable descending selection + feature build
// Register-resident bitonic sort: shfl for s<32, shared only for s>=32.
// ---------------------------------------------------------------------------
__global__ __launch_bounds__(256) void topk_feat_kernel(
    const float* __restrict__ images, const float* __restrict__ angles) {
  __shared__ unsigned int vbits[784];
  __shared__ unsigned int hist[256];
  __shared__ unsigned long long keys[256];
  __shared__ int sT;
  __shared__ int cnt;

  const int b = blockIdx.x;
  const int tid = threadIdx.x;
  const float* img = images + (size_t)b * 784;

  hist[tid] = 0u;
  if (tid == 0) cnt = 0;
  __syncthreads();

  // Pass 1: load values, histogram by 8-bit quantized bucket
  for (int i = tid; i < 784; i += 256) {
    float v = img[i];
    vbits[i] = __float_as_uint(v);
    int q = min(255, (int)(v * 256.0f));
    atomicAdd(&hist[q], 1u);
  }
  __syncthreads();

  // Pass 2: warp 0 finds threshold bucket T: count(q >= T) >= 200 > count(q > T)
  if (tid < 32) {
    unsigned int g = 0;
#pragma unroll
    for (int j = 0; j < 8; j++) g += hist[tid * 8 + j];
    unsigned int suf = g;
#pragma unroll
    for (int d = 1; d < 32; d <<= 1) {
      unsigned int o = __shfl_down_sync(0xffffffffu, suf, d);
      if (tid + d < 32) suf += o;
    }
    unsigned int m = __ballot_sync(0xffffffffu, suf >= 200u);
    int L = 31 - __clz(m);  // highest lane whose suffix-sum >= 200
    unsigned int sufN = __shfl_down_sync(0xffffffffu, suf, 1);
    if (tid == L) {
      unsigned int s = (L == 31) ? 0u : sufN;  // count strictly above lane L's buckets
      int T = 8 * L;
      for (int q = 8 * L + 7; q >= 8 * L; q--) {
        s += hist[q];
        if (s >= 200u) { T = q; break; }
      }
      sT = T;
    }
  }
  __syncthreads();

  keys[tid] = ~0ULL;  // sentinel: sorts last
  const int T = sT;
  __syncthreads();

  // Pass 3: compact candidates (q >= T). key = (~bits << 10) | idx
  // ascending sort => descending value, ascending index on ties (stable argsort(-v))
  for (int i = tid; i < 784; i += 256) {
    unsigned int vb = vbits[i];
    float v = __uint_as_float(vb);
    int q = min(255, (int)(v * 256.0f));
    if (q >= T) {
      int pos = atomicAdd(&cnt, 1);
      if (pos < 256)
        keys[pos] = (((unsigned long long)(~vb)) << 10) | (unsigned long long)i;
    }
  }
  __syncthreads();

  // Pass 4: register bitonic sort of 256 keys (all keys distinct: idx embedded)
  unsigned long long key = keys[tid];
#pragma unroll
  for (int k = 2; k <= 256; k <<= 1) {
#pragma unroll
    for (int s = k >> 1; s > 0; s >>= 1) {
      unsigned long long other;
      if (s < 32) {
        other = __shfl_xor_sync(0xffffffffu, key, s);
      } else {
        __syncthreads();   // prior reads of keys[] complete
        keys[tid] = key;
        __syncthreads();
        other = keys[tid ^ s];
      }
      bool up = ((tid & k) == 0);     // ascending block
      bool lower = ((tid & s) == 0);  // lower element of the pair
      unsigned long long mn = min(key, other);
      unsigned long long mx = max(key, other);
      key = (up == lower) ? mn : mx;
    }
  }

  // Pass 5: write features: [v(200) | (cx,cy)x200 | (cos,sin)x10]
  float* fo = g_feat + (size_t)b * DIN;
  if (tid < 200) {
    int idx = (int)(key & 1023ULL);
    unsigned int vb = ~((unsigned int)(key >> 10));
    float v = __uint_as_float(vb);
    int r = idx / 28;
    int c = idx - r * 28;
    float cx = (c < 14) ? (float)(c - 14) : (float)(c - 13);
    float cy = (r < 14) ? (float)(14 - r) : (float)(13 - r);
    if (v < 0.1f) { v = 0.f; cx = 0.f; cy = 0.f; }
    fo[tid] = v;
    fo[200 + 2 * tid] = cx;
    fo[201 + 2 * tid] = cy;
  } else if (tid < 210) {
    int d = tid - 200;
    float a = angles[(size_t)b * 10 + d];
    float sn, cs;
    sincosf(a, &sn, &cs);
    fo[600 + 2 * d] = cs;
    fo[601 + 2 * d] = sn;
  }
}

// ---------------------------------------------------------------------------
// Kernel B: fused 4-layer MLP + 2x2 Gram-Schmidt epilogue
// 32 batch rows per block (1024 blocks), 96 threads, 4x8 register micro-tile
// ---------------------------------------------------------------------------
__global__ __launch_bounds__(96) void mlp_kernel(
    const float* __restrict__ W1, const float* __restrict__ b1,
    const float* __restrict__ W2, const float* __restrict__ b2,
    const float* __restrict__ W3, const float* __restrict__ b3,
    const float* __restrict__ W4, const float* __restrict__ b4,
    float* __restrict__ outp) {
  __shared__ float fbuf[32 * 33];   // 31-wide k-slab of feat, padded rows
  __shared__ float hbuf[32 * 97];   // activations, padded rows

  const int tid = threadIdx.x;
  const int tc = tid % 12;   // 12 col-groups x 8 cols = 96
  const int tr = tid / 12;   // 8 row-groups  x 4 rows = 32
  const int row0 = blockIdx.x * 32;
  const float* fptr = g_feat + (size_t)row0 * DIN;

  float acc[4][8];
#pragma unroll
  for (int i = 0; i < 4; i++)
#pragma unroll
    for (int j = 0; j < 8; j++) acc[i][j] = 0.f;

  // ---- Layer 1: 620 -> 96, k streamed in 20 slabs of 31 ----
  for (int ks = 0; ks < 620; ks += 31) {
    __syncthreads();
    for (int idx = tid; idx < 32 * 31; idx += 96) {
      int r = idx / 31;
      int kk = idx - r * 31;
      fbuf[r * 33 + kk] = fptr[(size_t)r * DIN + ks + kk];
    }
    __syncthreads();
#pragma unroll 2
    for (int kk = 0; kk < 31; kk++) {
      int k = ks + kk;
      float4 wa = *(const float4*)(W1 + (size_t)k * 96 + tc * 8);
      float4 wb = *(const float4*)(W1 + (size_t)k * 96 + tc * 8 + 4);
      float f[4];
#pragma unroll
      for (int i = 0; i < 4; i++) f[i] = fbuf[(tr * 4 + i) * 33 + kk];
      float w[8] = {wa.x, wa.y, wa.z, wa.w, wb.x, wb.y, wb.z, wb.w};
#pragma unroll
      for (int i = 0; i < 4; i++)
#pragma unroll
        for (int j = 0; j < 8; j++) acc[i][j] = fmaf(f[i], w[j], acc[i][j]);
    }
  }
  __syncthreads();
  {
    float4 ba = *(const float4*)(b1 + tc * 8);
    float4 bb = *(const float4*)(b1 + tc * 8 + 4);
    float bl[8] = {ba.x, ba.y, ba.z, ba.w, bb.x, bb.y, bb.z, bb.w};
#pragma unroll
    for (int i = 0; i < 4; i++)
#pragma unroll
      for (int j = 0; j < 8; j++)
        hbuf[(tr * 4 + i) * 97 + tc * 8 + j] = fmaxf(acc[i][j] + bl[j], 0.f);
  }
  __syncthreads();

  // ---- Layers 2 & 3: 96 -> 96 (accumulate in regs, then overwrite hbuf) ----
  for (int layer = 0; layer < 2; layer++) {
    const float* W = layer ? W3 : W2;
    const float* bp = layer ? b3 : b2;
    float a2[4][8];
#pragma unroll
    for (int i = 0; i < 4; i++)
#pragma unroll
      for (int j = 0; j < 8; j++) a2[i][j] = 0.f;
#pragma unroll 2
    for (int k = 0; k < 96; k++) {
      float4 wa = *(const float4*)(W + (size_t)k * 96 + tc * 8);
      float4 wb = *(const float4*)(W + (size_t)k * 96 + tc * 8 + 4);
      float f[4];
#pragma unroll
      for (int i = 0; i < 4; i++) f[i] = hbuf[(tr * 4 + i) * 97 + k];
      float w[8] = {wa.x, wa.y, wa.z, wa.w, wb.x, wb.y, wb.z, wb.w};
#pragma unroll
      for (int i = 0; i < 4; i++)
#pragma unroll
        for (int j = 0; j < 8; j++) a2[i][j] = fmaf(f[i], w[j], a2[i][j]);
    }
    __syncthreads();  // all reads of hbuf complete before overwrite
    {
      float4 ba = *(const float4*)(bp + tc * 8);
      float4 bb = *(const float4*)(bp + tc * 8 + 4);
      float bl[8] = {ba.x, ba.y, ba.z, ba.w, bb.x, bb.y, bb.z, bb.w};
#pragma unroll
      for (int i = 0; i < 4; i++)
#pragma unroll
        for (int j = 0; j < 8; j++)
          hbuf[(tr * 4 + i) * 97 + tc * 8 + j] = fmaxf(a2[i][j] + bl[j], 0.f);
    }
    __syncthreads();
  }

  // ---- Layer 4 (96 -> 4) + Gram-Schmidt epilogue, one thread per row ----
  if (tid < 32) {
    float o0 = 0.f, o1 = 0.f, o2 = 0.f, o3 = 0.f;
#pragma unroll 4
    for (int k = 0; k < 96; k++) {
      float hv = hbuf[tid * 97 + k];
      float4 w = *(const float4*)(W4 + (size_t)k * 4);
      o0 = fmaf(hv, w.x, o0);
      o1 = fmaf(hv, w.y, o1);
      o2 = fmaf(hv, w.z, o2);
      o3 = fmaf(hv, w.w, o3);
    }
    float4 bv = *(const float4*)(b4);
    o0 += bv.x; o1 += bv.y; o2 += bv.z; o3 += bv.w;

    // gs = out^T: c0 = (o0,o1), c1 = (o2,o3)
    float n0 = 1.0f / sqrtf(o0 * o0 + o1 * o1);
    float e0x = o0 * n0, e0y = o1 * n0;
    float dt = e0x * o2 + e0y * o3;
    float u1x = o2 - dt * e0x, u1y = o3 - dt * e0y;
    float n1 = 1.0f / sqrtf(u1x * u1x + u1y * u1y);
    float e1x = u1x * n1, e1y = u1y * n1;
    float det = e0x * e1y - e1x * e0y;

    float* po = outp + (size_t)(row0 + tid) * 4;
    po[0] = e0x * det;  // q[0][0]*det
    po[1] = e1x;        // q[0][1]
    po[2] = e0y * det;  // q[1][0]*det
    po[3] = e1y;        // q[1][1]
  }
}

// ---------------------------------------------------------------------------
extern "C" void kernel_launch(void* const* d_in, const int* in_sizes, int n_in,
                              void* d_out, int out_size) {
  (void)in_sizes; (void)n_in; (void)out_size;
  const float* images = (const float*)d_in[0];
  const float* angles = (const float*)d_in[1];
  const float* W1 = (const float*)d_in[2];
  const float* b1 = (const float*)d_in[3];
  const float* W2 = (const float*)d_in[4];
  const float* b2 = (const float*)d_in[5];
  const float* W3 = (const float*)d_in[6];
  const float* b3 = (const float*)d_in[7];
  const float* W4 = (const float*)d_in[8];
  const float* b4 = (const float*)d_in[9];
  float* outp = (float*)d_out;

  topk_feat_kernel<<<NIMG, 256>>>(images, angles);
  mlp_kernel<<<NIMG / 32, 96>>>(W1, b1, W2, b2, W3, b3, W4, b4, outp);
}

// round 3
// speedup vs baseline: 1.9131x; 1.2772x over previous
#include <cuda_runtime.h>
#include <math.h>

#define NIMG 32768
#define DIN  620

// 81.3 MB feature scratch (device global: allocation-free per harness rules)
__device__ float g_feat[(size_t)NIMG * DIN];

// ---------------------------------------------------------------------------
// Kernel A: per-image top-200 stable descending selection + feature build.
// Sort-free: histogram -> per-bin suffix counts -> exact stable rank of the
// ~205 candidates via within-bucket comparisons -> direct scatter by rank.
// ---------------------------------------------------------------------------
__global__ __launch_bounds__(256) void topk_feat_kernel(
    const float* __restrict__ images, const float* __restrict__ angles) {
  __shared__ unsigned int vbits[784];
  __shared__ unsigned int hist[256];
  __shared__ unsigned int above[256];     // # elements in buckets > q
  __shared__ unsigned int cursor[256];
  __shared__ unsigned long long bucketed[784];
  __shared__ unsigned int gsuf[33];       // suffix sums of 8-bin groups
  __shared__ int sT;

  const int b = blockIdx.x;
  const int tid = threadIdx.x;
  const float* img = images + (size_t)b * 784;
  float* fo = g_feat + (size_t)b * DIN;

  // Noise features (independent of the selection)
  if (tid < 10) {
    float a = angles[(size_t)b * 10 + tid];
    float sn, cs;
    sincosf(a, &sn, &cs);
    fo[600 + 2 * tid] = cs;
    fo[601 + 2 * tid] = sn;
  }

  hist[tid] = 0u;
  cursor[tid] = 0u;
  __syncthreads();

  // Pass 1: load values, histogram by 8-bit quantized bucket
  for (int i = tid; i < 784; i += 256) {
    float v = img[i];
    vbits[i] = __float_as_uint(v);
    int q = min(255, (int)(v * 256.0f));
    atomicAdd(&hist[q], 1u);
  }
  __syncthreads();

  // Pass 2a: warp 0 computes inclusive suffix sums over 8-bin groups
  if (tid < 32) {
    unsigned int g = 0;
#pragma unroll
    for (int j = 0; j < 8; j++) g += hist[tid * 8 + j];
    unsigned int suf = g;
#pragma unroll
    for (int d = 1; d < 32; d <<= 1) {
      unsigned int o = __shfl_down_sync(0xffffffffu, suf, d);
      if (tid + d < 32) suf += o;
    }
    gsuf[tid] = suf;       // count in bins >= tid*8
    if (tid == 0) gsuf[32] = 0u;
  }
  __syncthreads();

  // Pass 2b: per-bin "above" counts; detect threshold bin T
  {
    int g = tid >> 3;
    unsigned int a = gsuf[g + 1];
    int hi8 = g * 8 + 7;
    for (int q = tid + 1; q <= hi8; q++) a += hist[q];
    above[tid] = a;
    if (a < 200u && a + hist[tid] >= 200u) sT = tid;  // exactly one bin
  }
  __syncthreads();
  const int T = sT;

  // Pass 3: scatter candidates (q >= T) into bucket-grouped slots.
  // Slot order within a bucket is nondeterministic (atomic), but ranks are
  // recomputed deterministically from (value, idx) below.
  for (int i = tid; i < 784; i += 256) {
    unsigned int vb = vbits[i];
    float v = __uint_as_float(vb);
    int q = min(255, (int)(v * 256.0f));
    if (q >= T) {
      unsigned int pos = above[q] + atomicAdd(&cursor[q], 1u);
      bucketed[pos] = ((unsigned long long)vb << 32) | (unsigned int)i;
    }
  }
  __syncthreads();

  // Pass 4: exact stable rank of each candidate; write features at rank.
  const int ncand = (int)(above[T] + hist[T]);
  for (int s = tid; s < ncand; s += 256) {
    unsigned long long e = bucketed[s];
    unsigned int vb = (unsigned int)(e >> 32);
    unsigned int idx = (unsigned int)(e & 0xffffffffu);
    float v = __uint_as_float(vb);
    int q = min(255, (int)(v * 256.0f));
    int lo = (int)above[q];
    int hi = lo + (int)hist[q];
    int rank = lo;
    for (int m = lo; m < hi; m++) {
      if (m == s) continue;
      unsigned long long me = bucketed[m];
      unsigned int mvb = (unsigned int)(me >> 32);
      unsigned int midx = (unsigned int)(me & 0xffffffffu);
      if (mvb > vb || (mvb == vb && midx < idx)) rank++;
    }
    if (rank < 200) {
      int r = (int)idx / 28;
      int c = (int)idx - r * 28;
      float cx = (c < 14) ? (float)(c - 14) : (float)(c - 13);
      float cy = (r < 14) ? (float)(14 - r) : (float)(13 - r);
      float vv = v;
      if (vv < 0.1f) { vv = 0.f; cx = 0.f; cy = 0.f; }
      fo[rank] = vv;
      fo[200 + 2 * rank] = cx;
      fo[201 + 2 * rank] = cy;
    }
  }
}

// ---------------------------------------------------------------------------
// Kernel B: fused 4-layer MLP + 2x2 Gram-Schmidt epilogue
// 64 rows/block (512 blocks), 192 threads, 8x4 micro-tile.
// Activations stored k-major (stride 68) so row-reads are aligned LDS.128.
// ---------------------------------------------------------------------------
__global__ __launch_bounds__(192) void mlp_kernel(
    const float* __restrict__ W1, const float* __restrict__ b1,
    const float* __restrict__ W2, const float* __restrict__ b2,
    const float* __restrict__ W3, const float* __restrict__ b3,
    const float* __restrict__ W4, const float* __restrict__ b4,
    float* __restrict__ outp) {
  __shared__ __align__(16) float fbuf[31 * 68];  // k-major feat slab
  __shared__ __align__(16) float hbuf[96 * 68];  // k-major activations

  const int tid = threadIdx.x;
  const int tc = tid % 24;   // 24 col-groups x 4 cols = 96
  const int tr = tid / 24;   // 8 row-groups  x 8 rows = 64
  const int row0 = blockIdx.x * 64;
  const float* fptr = g_feat + (size_t)row0 * DIN;

  float acc[8][4];
#pragma unroll
  for (int i = 0; i < 8; i++)
#pragma unroll
    for (int j = 0; j < 4; j++) acc[i][j] = 0.f;

  // ---- Layer 1: 620 -> 96, k streamed in 20 slabs of 31 ----
  for (int ks = 0; ks < 620; ks += 31) {
    __syncthreads();
    for (int idx = tid; idx < 64 * 31; idx += 192) {
      int r = idx / 31;
      int kk = idx - r * 31;
      fbuf[kk * 68 + r] = fptr[(size_t)r * DIN + ks + kk];
    }
    __syncthreads();
#pragma unroll 2
    for (int kk = 0; kk < 31; kk++) {
      float4 w = *(const float4*)(W1 + (size_t)(ks + kk) * 96 + tc * 4);
      float4 fa = *(const float4*)(&fbuf[kk * 68 + tr * 8]);
      float4 fb = *(const float4*)(&fbuf[kk * 68 + tr * 8 + 4]);
      float f[8] = {fa.x, fa.y, fa.z, fa.w, fb.x, fb.y, fb.z, fb.w};
      float wv[4] = {w.x, w.y, w.z, w.w};
#pragma unroll
      for (int i = 0; i < 8; i++)
#pragma unroll
        for (int j = 0; j < 4; j++) acc[i][j] = fmaf(f[i], wv[j], acc[i][j]);
    }
  }
  __syncthreads();
  {
    float4 bv = *(const float4*)(b1 + tc * 4);
    float bl[4] = {bv.x, bv.y, bv.z, bv.w};
#pragma unroll
    for (int j = 0; j < 4; j++) {
      float4 s0, s1;
      s0.x = fmaxf(acc[0][j] + bl[j], 0.f);
      s0.y = fmaxf(acc[1][j] + bl[j], 0.f);
      s0.z = fmaxf(acc[2][j] + bl[j], 0.f);
      s0.w = fmaxf(acc[3][j] + bl[j], 0.f);
      s1.x = fmaxf(acc[4][j] + bl[j], 0.f);
      s1.y = fmaxf(acc[5][j] + bl[j], 0.f);
      s1.z = fmaxf(acc[6][j] + bl[j], 0.f);
      s1.w = fmaxf(acc[7][j] + bl[j], 0.f);
      *(float4*)(&hbuf[(tc * 4 + j) * 68 + tr * 8]) = s0;
      *(float4*)(&hbuf[(tc * 4 + j) * 68 + tr * 8 + 4]) = s1;
    }
  }
  __syncthreads();

  // ---- Layers 2 & 3: 96 -> 96 (accumulate in regs, then overwrite hbuf) ----
  for (int layer = 0; layer < 2; layer++) {
    const float* W = layer ? W3 : W2;
    const float* bp = layer ? b3 : b2;
    float a2[8][4];
#pragma unroll
    for (int i = 0; i < 8; i++)
#pragma unroll
      for (int j = 0; j < 4; j++) a2[i][j] = 0.f;
#pragma unroll 2
    for (int k = 0; k < 96; k++) {
      float4 w = *(const float4*)(W + (size_t)k * 96 + tc * 4);
      float4 fa = *(const float4*)(&hbuf[k * 68 + tr * 8]);
      float4 fb = *(const float4*)(&hbuf[k * 68 + tr * 8 + 4]);
      float f[8] = {fa.x, fa.y, fa.z, fa.w, fb.x, fb.y, fb.z, fb.w};
      float wv[4] = {w.x, w.y, w.z, w.w};
#pragma unroll
      for (int i = 0; i < 8; i++)
#pragma unroll
        for (int j = 0; j < 4; j++) a2[i][j] = fmaf(f[i], wv[j], a2[i][j]);
    }
    __syncthreads();  // all reads of hbuf complete before overwrite
    {
      float4 bv = *(const float4*)(bp + tc * 4);
      float bl[4] = {bv.x, bv.y, bv.z, bv.w};
#pragma unroll
      for (int j = 0; j < 4; j++) {
        float4 s0, s1;
        s0.x = fmaxf(a2[0][j] + bl[j], 0.f);
        s0.y = fmaxf(a2[1][j] + bl[j], 0.f);
        s0.z = fmaxf(a2[2][j] + bl[j], 0.f);
        s0.w = fmaxf(a2[3][j] + bl[j], 0.f);
        s1.x = fmaxf(a2[4][j] + bl[j], 0.f);
        s1.y = fmaxf(a2[5][j] + bl[j], 0.f);
        s1.z = fmaxf(a2[6][j] + bl[j], 0.f);
        s1.w = fmaxf(a2[7][j] + bl[j], 0.f);
        *(float4*)(&hbuf[(tc * 4 + j) * 68 + tr * 8]) = s0;
        *(float4*)(&hbuf[(tc * 4 + j) * 68 + tr * 8 + 4]) = s1;
      }
    }
    __syncthreads();
  }

  // ---- Layer 4 (96 -> 4) + Gram-Schmidt epilogue, one thread per row ----
  if (tid < 64) {
    float o0 = 0.f, o1 = 0.f, o2 = 0.f, o3 = 0.f;
#pragma unroll 4
    for (int k = 0; k < 96; k++) {
      float hv = hbuf[k * 68 + tid];
      float4 w = *(const float4*)(W4 + (size_t)k * 4);
      o0 = fmaf(hv, w.x, o0);
      o1 = fmaf(hv, w.y, o1);
      o2 = fmaf(hv, w.z, o2);
      o3 = fmaf(hv, w.w, o3);
    }
    float4 bv = *(const float4*)(b4);
    o0 += bv.x; o1 += bv.y; o2 += bv.z; o3 += bv.w;

    // gs = out^T: c0 = (o0,o1), c1 = (o2,o3)
    float n0 = 1.0f / sqrtf(o0 * o0 + o1 * o1);
    float e0x = o0 * n0, e0y = o1 * n0;
    float dt = e0x * o2 + e0y * o3;
    float u1x = o2 - dt * e0x, u1y = o3 - dt * e0y;
    float n1 = 1.0f / sqrtf(u1x * u1x + u1y * u1y);
    float e1x = u1x * n1, e1y = u1y * n1;
    float det = e0x * e1y - e1x * e0y;

    float* po = outp + (size_t)(row0 + tid) * 4;
    po[0] = e0x * det;  // q[0][0]*det
    po[1] = e1x;        // q[0][1]
    po[2] = e0y * det;  // q[1][0]*det
    po[3] = e1y;        // q[1][1]
  }
}

// ---------------------------------------------------------------------------
extern "C" void kernel_launch(void* const* d_in, const int* in_sizes, int n_in,
                              void* d_out, int out_size) {
  (void)in_sizes; (void)n_in; (void)out_size;
  const float* images = (const float*)d_in[0];
  const float* angles = (const float*)d_in[1];
  const float* W1 = (const float*)d_in[2];
  const float* b1 = (const float*)d_in[3];
  const float* W2 = (const float*)d_in[4];
  const float* b2 = (const float*)d_in[5];
  const float* W3 = (const float*)d_in[6];
  const float* b3 = (const float*)d_in[7];
  const float* W4 = (const float*)d_in[8];
  const float* b4 = (const float*)d_in[9];
  float* outp = (float*)d_out;

  topk_feat_kernel<<<NIMG, 256>>>(images, angles);
  mlp_kernel<<<NIMG / 64, 192>>>(W1, b1, W2, b2, W3, b3, W4, b4, outp);
}